// round 15
// baseline (speedup 1.0000x reference)
#include <cuda_runtime.h>
#include <math.h>

#define TBL    524288u                 // T = 2^19 entries per level
#define MASK8  ((TBL - 1u) * 8u)       // byte-space mask
#define MASK16 (MASK8 & ~8u)           // 16B-aligned byte mask
#define PR1    2654435761u
#define PR2    805459861u

#define NPTS   2097152u
#define BX     32                      // spatial buckets per axis
#define NBKT   (BX * BX * BX)          // 32768 buckets (~64 pts each)
#define CAP    128u                    // slots per bucket (mean 64 + 8 sigma)

struct Res16 { int r[16]; };

// ---- device scratch (static only; no cudaMalloc allowed) ----
// g_cnt: zeroed at module load (.bss); the encode kernel re-zeroes its two
// buckets at the end of every run so each graph replay starts clean.
__device__ unsigned g_cnt[NBKT];
__device__ float4   g_xs[NBKT * CAP];    // bucketed {x,y,z, bits(orig idx)} (64MB)

__device__ __forceinline__ float2 lerp2(float2 a, float2 b, float t) {
    return make_float2(fmaf(t, b.x - a.x, a.x), fmaf(t, b.y - a.y, a.y));
}

// One level of hash-grid trilinear interpolation; byte-space hashing.
// EVEN ix: both x-corners sit in one aligned 16B block -> single LDG.128.
// (Exact R10/R14 code shape -- ptxas schedules this form with full load
// batching; R12/R13 perturbations both regressed. Do not "improve".)
__device__ __forceinline__ float2 enc_level(
    const char* __restrict__ base, float px, float py, float pz, float r)
{
    float xs = px * r, ys = py * r, zs = pz * r;
    int ix = (int)xs, iy = (int)ys, iz = (int)zs;
    float fx = xs - (float)ix;
    float fy = ys - (float)iy;
    float fz = zs - (float)iz;

    unsigned hx0 = ((unsigned)ix) << 3;
    unsigned hy0 = (unsigned)iy * (PR1 * 8u);
    unsigned hy1 = hy0 + (PR1 * 8u);
    unsigned hz0 = (unsigned)iz * (PR2 * 8u);
    unsigned hz1 = hz0 + (PR2 * 8u);
    unsigned a00 = hy0 ^ hz0;
    unsigned a01 = hy0 ^ hz1;
    unsigned a10 = hy1 ^ hz0;
    unsigned a11 = hy1 ^ hz1;

    float2 e000, e001, e010, e011, e100, e101, e110, e111;

    if ((hx0 & 8u) == 0u) {
        float4 v00 = __ldg((const float4*)(base + ((hx0 ^ a00) & MASK16)));
        float4 v01 = __ldg((const float4*)(base + ((hx0 ^ a01) & MASK16)));
        float4 v10 = __ldg((const float4*)(base + ((hx0 ^ a10) & MASK16)));
        float4 v11 = __ldg((const float4*)(base + ((hx0 ^ a11) & MASK16)));
        bool s00 = (a00 & 8u) != 0u;
        bool s01 = (a01 & 8u) != 0u;
        bool s10 = (a10 & 8u) != 0u;
        bool s11 = (a11 & 8u) != 0u;
        e000 = s00 ? make_float2(v00.z, v00.w) : make_float2(v00.x, v00.y);
        e100 = s00 ? make_float2(v00.x, v00.y) : make_float2(v00.z, v00.w);
        e001 = s01 ? make_float2(v01.z, v01.w) : make_float2(v01.x, v01.y);
        e101 = s01 ? make_float2(v01.x, v01.y) : make_float2(v01.z, v01.w);
        e010 = s10 ? make_float2(v10.z, v10.w) : make_float2(v10.x, v10.y);
        e110 = s10 ? make_float2(v10.x, v10.y) : make_float2(v10.z, v10.w);
        e011 = s11 ? make_float2(v11.z, v11.w) : make_float2(v11.x, v11.y);
        e111 = s11 ? make_float2(v11.x, v11.y) : make_float2(v11.z, v11.w);
    } else {
        unsigned hx1 = hx0 + 8u;
        e000 = __ldg((const float2*)(base + ((hx0 ^ a00) & MASK8)));
        e001 = __ldg((const float2*)(base + ((hx0 ^ a01) & MASK8)));
        e010 = __ldg((const float2*)(base + ((hx0 ^ a10) & MASK8)));
        e011 = __ldg((const float2*)(base + ((hx0 ^ a11) & MASK8)));
        e100 = __ldg((const float2*)(base + ((hx1 ^ a00) & MASK8)));
        e101 = __ldg((const float2*)(base + ((hx1 ^ a01) & MASK8)));
        e110 = __ldg((const float2*)(base + ((hx1 ^ a10) & MASK8)));
        e111 = __ldg((const float2*)(base + ((hx1 ^ a11) & MASK8)));
    }

    float2 c00 = lerp2(e000, e100, fx);
    float2 c01 = lerp2(e001, e101, fx);
    float2 c10 = lerp2(e010, e110, fx);
    float2 c11 = lerp2(e011, e111, fx);
    float2 c0  = lerp2(c00, c10, fy);
    float2 c1  = lerp2(c01, c11, fy);
    return lerp2(c0, c1, fz);
}

// interleave low 10 bits of v with two zero bits (Morton helper)
__device__ __forceinline__ unsigned part1by2(unsigned v) {
    v = (v | (v << 16)) & 0x030000FFu;
    v = (v | (v << 8))  & 0x0300F00Fu;
    v = (v | (v << 4))  & 0x030C30C3u;
    v = (v | (v << 2))  & 0x09249249u;
    return v;
}

__device__ __forceinline__ unsigned bucket_key(float px, float py, float pz) {
    unsigned bx = min((unsigned)(px * (float)BX), (unsigned)(BX - 1));
    unsigned by = min((unsigned)(py * (float)BX), (unsigned)(BX - 1));
    unsigned bz = min((unsigned)(pz * (float)BX), (unsigned)(BX - 1));
    return part1by2(bx) | (part1by2(by) << 1) | (part1by2(bz) << 2);  // < 32768
}

// ---- single-pass bucketing: 8 points per thread, atomics batched first
// (8 independent atomic->store chains in flight per thread). Bound by the
// LSU atomic-accept floor (~4 cyc/op), not by latency -- do not add ILP.
__global__ void scatter8_kernel(const float* __restrict__ x, unsigned nocts) {
    unsigned q = blockIdx.x * blockDim.x + threadIdx.x;
    if (q >= nocts) return;
    const float4* xv = (const float4*)(x + 24u * q);
    float4 v0 = __ldg(xv + 0), v1 = __ldg(xv + 1), v2 = __ldg(xv + 2);
    float4 v3 = __ldg(xv + 3), v4 = __ldg(xv + 4), v5 = __ldg(xv + 5);
    float vals[24] = {v0.x, v0.y, v0.z, v0.w, v1.x, v1.y, v1.z, v1.w,
                      v2.x, v2.y, v2.z, v2.w, v3.x, v3.y, v3.z, v3.w,
                      v4.x, v4.y, v4.z, v4.w, v5.x, v5.y, v5.z, v5.w};
    unsigned key[8], pos[8];
    #pragma unroll
    for (int i = 0; i < 8; i++)
        key[i] = bucket_key(vals[3 * i], vals[3 * i + 1], vals[3 * i + 2]);
    #pragma unroll
    for (int i = 0; i < 8; i++)
        pos[i] = atomicAdd(&g_cnt[key[i]], 1u);
    unsigned i0 = 8u * q;
    #pragma unroll
    for (int i = 0; i < 8; i++) {
        if (pos[i] < CAP)
            g_xs[key[i] * CAP + pos[i]] =
                make_float4(vals[3 * i], vals[3 * i + 1], vals[3 * i + 2],
                            __uint_as_float(i0 + (unsigned)i));
    }
}

// ---- encode over bucket slots ----
// Grid covers all NBKT*CAP slots; each warp's 32 slots lie inside ONE
// bucket (CAP=128 -> 4 warps/bucket) so every gather instruction has all
// active lanes at the same level on one spatial bucket's points ->
// maximal cross-lane 128B-line merging (the binding resource).
// Output path: 8x8 in-register butterfly transpose within lane-groups of 8
// so each STG.128 instruction has 8 lanes co-writing one row's full 128B
// -> 4 distinct lines per STG (stores: 1 wf/pt).
// Empty warps skip the body (branch-around, NOT return: all warps must
// reach the final barrier). Tail: this CTA's 2 buckets get their counters
// re-zeroed for the next graph replay -- counter reads all happen before
// the barrier and only this CTA touches these two counters in encode.
__global__ void __launch_bounds__(256, 3) encode_bucket_kernel(
    const float* __restrict__ emb,
    float* __restrict__ out,
    Res16 rr)
{
    unsigned idx = blockIdx.x * 256u + threadIdx.x;   // global slot
    unsigned bucket = idx >> 7;                       // CAP = 128
    unsigned slot   = idx & 127u;
    unsigned lane   = threadIdx.x & 31u;

    unsigned cnt = min(__ldg(g_cnt + bucket), CAP);
    bool valid = slot < cnt;
    unsigned vmask = __ballot_sync(0xFFFFFFFFu, valid);

    if (vmask != 0u) {                                // whole warp empty -> skip body
        float4 p = make_float4(0.f, 0.f, 0.f, 0.f);
        if (valid) p = g_xs[idx];
        unsigned pidx = __float_as_uint(p.w);

        const char* base = (const char*)emb;
        float4 c[8];                                  // chunk j = levels 2j,2j+1
        #pragma unroll
        for (int j = 0; j < 8; j++) c[j] = make_float4(0.f, 0.f, 0.f, 0.f);
        if (valid) {
            #pragma unroll
            for (int j = 0; j < 8; j++) {
                float2 f0 = enc_level(base + (size_t)(2 * j) * (size_t)(TBL * 8u),
                                      p.x, p.y, p.z, (float)rr.r[2 * j]);
                float2 f1 = enc_level(base + (size_t)(2 * j + 1) * (size_t)(TBL * 8u),
                                      p.x, p.y, p.z, (float)rr.r[2 * j + 1]);
                c[j] = make_float4(f0.x, f0.y, f1.x, f1.y);
            }
        }

        // 8x8 transpose within groups of 8 lanes: element (lane p, slot t)
        // -> (lane t, slot p) via 3 xor-swap stages (moves iff ((p^t)&m)!=0).
        #pragma unroll
        for (int m = 1; m < 8; m <<= 1) {
            bool upper = (lane & (unsigned)m) != 0u;
            #pragma unroll
            for (int s0 = 0; s0 < 8; s0++) {
                if (s0 & m) continue;
                int s1 = s0 | m;
                float4 send = upper ? c[s0] : c[s1];
                float4 recv;
                recv.x = __shfl_xor_sync(0xFFFFFFFFu, send.x, m);
                recv.y = __shfl_xor_sync(0xFFFFFFFFu, send.y, m);
                recv.z = __shfl_xor_sync(0xFFFFFFFFu, send.z, m);
                recv.w = __shfl_xor_sync(0xFFFFFFFFu, send.w, m);
                if (upper) c[s0] = recv; else c[s1] = recv;
            }
        }
        // now lane (g,j): c[k] = chunk j (cols 4j..4j+3) of point 8g+k

        unsigned j = lane & 7u;
        unsigned gb = lane & 24u;
        #pragma unroll
        for (unsigned k = 0; k < 8; k++) {
            unsigned src = gb + k;
            unsigned rowpt = __shfl_sync(0xFFFFFFFFu, pidx, src);
            if ((vmask >> src) & 1u)
                *(float4*)(out + (size_t)rowpt * 32u + 4u * j) = c[k];
        }
    }

    // reset counters for the next graph replay (this CTA owns exactly the
    // two buckets its 256 slots cover; all cnt reads happened above).
    __syncthreads();
    if ((threadIdx.x & 127u) == 0u) g_cnt[bucket] = 0u;
}

// ---- fallback (unsorted) for unexpected sizes ----
__global__ void __launch_bounds__(256, 4) hashenc_fallback_kernel(
    const float* __restrict__ x,
    const float* __restrict__ emb,
    float* __restrict__ out,
    unsigned npts, Res16 rr)
{
    unsigned tid = blockIdx.x * 256u + threadIdx.x;
    unsigned pt = tid >> 3;
    if (pt >= npts) return;
    unsigned chunk = tid & 7u;
    unsigned lvl = chunk * 2u;

    float px = __ldg(x + 3u * pt + 0u);
    float py = __ldg(x + 3u * pt + 1u);
    float pz = __ldg(x + 3u * pt + 2u);

    const char* base0 = (const char*)emb + (size_t)lvl * (size_t)(TBL * 8u);
    float r0 = (float)rr.r[lvl];
    float r1 = (float)rr.r[lvl + 1u];

    float2 f0 = enc_level(base0, px, py, pz, r0);
    float2 f1 = enc_level(base0 + (size_t)(TBL * 8u), px, py, pz, r1);

    float4 o = make_float4(f0.x, f0.y, f1.x, f1.y);
    *(float4*)(out + (size_t)pt * 32u + chunk * 4u) = o;
}

extern "C" void kernel_launch(void* const* d_in, const int* in_sizes, int n_in,
                              void* d_out, int out_size)
{
    const float* x   = (const float*)d_in[0];   // [2097152, 3] f32
    const float* emb = (const float*)d_in[1];   // [16, 524288, 2] f32
    float* out = (float*)d_out;                 // [2097152, 32] f32

    unsigned npts = (unsigned)(in_sizes[0] / 3);

    // Resolutions via the exact reference formula in double precision
    // (floor margins as small as 0.004 -> do NOT hardcode).
    Res16 rr;
    double b = exp((log(2048.0) - log(16.0)) / 15.0);
    for (int i = 0; i < 16; i++)
        rr.r[i] = (int)floor(16.0 * pow(b, (double)i));

    if (npts == NPTS) {
        unsigned nocts = npts / 8u;
        scatter8_kernel<<<(nocts + 255u) / 256u, 256>>>(x, nocts);
        encode_bucket_kernel<<<(NBKT * CAP) / 256u, 256>>>(emb, out, rr);
    } else {
        unsigned total = npts * 8u;
        hashenc_fallback_kernel<<<(total + 255u) / 256u, 256>>>(x, emb, out, npts, rr);
    }
}

// round 16
// speedup vs baseline: 1.0742x; 1.0742x over previous
#include <cuda_runtime.h>
#include <math.h>

#define TBL    524288u                 // T = 2^19 entries per level
#define MASK8  ((TBL - 1u) * 8u)       // byte-space mask
#define MASK16 (MASK8 & ~8u)           // 16B-aligned byte mask
#define PR1    2654435761u
#define PR2    805459861u

#define NPTS   2097152u
#define BX     32                      // spatial buckets per axis
#define NBKT   (BX * BX * BX)          // 32768 buckets (~64 pts each)
#define CAP    128u                    // slots per bucket (mean 64 + 8 sigma)

struct Res16 { int r[16]; };

// ---- device scratch (static only; no cudaMalloc allowed) ----
__device__ unsigned g_cnt[NBKT];
__device__ float4   g_xs[NBKT * CAP];    // bucketed {x,y,z, bits(orig idx)} (64MB)

__device__ __forceinline__ float2 lerp2(float2 a, float2 b, float t) {
    return make_float2(fmaf(t, b.x - a.x, a.x), fmaf(t, b.y - a.y, a.y));
}

// One level of hash-grid trilinear interpolation; byte-space hashing.
// EVEN ix: both x-corners sit in one aligned 16B block -> single LDG.128.
// (Exact R10/R14 code shape -- ptxas schedules this form with full load
// batching; R12/R13/R15 perturbations all regressed. Do not "improve".)
__device__ __forceinline__ float2 enc_level(
    const char* __restrict__ base, float px, float py, float pz, float r)
{
    float xs = px * r, ys = py * r, zs = pz * r;
    int ix = (int)xs, iy = (int)ys, iz = (int)zs;
    float fx = xs - (float)ix;
    float fy = ys - (float)iy;
    float fz = zs - (float)iz;

    unsigned hx0 = ((unsigned)ix) << 3;
    unsigned hy0 = (unsigned)iy * (PR1 * 8u);
    unsigned hy1 = hy0 + (PR1 * 8u);
    unsigned hz0 = (unsigned)iz * (PR2 * 8u);
    unsigned hz1 = hz0 + (PR2 * 8u);
    unsigned a00 = hy0 ^ hz0;
    unsigned a01 = hy0 ^ hz1;
    unsigned a10 = hy1 ^ hz0;
    unsigned a11 = hy1 ^ hz1;

    float2 e000, e001, e010, e011, e100, e101, e110, e111;

    if ((hx0 & 8u) == 0u) {
        float4 v00 = __ldg((const float4*)(base + ((hx0 ^ a00) & MASK16)));
        float4 v01 = __ldg((const float4*)(base + ((hx0 ^ a01) & MASK16)));
        float4 v10 = __ldg((const float4*)(base + ((hx0 ^ a10) & MASK16)));
        float4 v11 = __ldg((const float4*)(base + ((hx0 ^ a11) & MASK16)));
        bool s00 = (a00 & 8u) != 0u;
        bool s01 = (a01 & 8u) != 0u;
        bool s10 = (a10 & 8u) != 0u;
        bool s11 = (a11 & 8u) != 0u;
        e000 = s00 ? make_float2(v00.z, v00.w) : make_float2(v00.x, v00.y);
        e100 = s00 ? make_float2(v00.x, v00.y) : make_float2(v00.z, v00.w);
        e001 = s01 ? make_float2(v01.z, v01.w) : make_float2(v01.x, v01.y);
        e101 = s01 ? make_float2(v01.x, v01.y) : make_float2(v01.z, v01.w);
        e010 = s10 ? make_float2(v10.z, v10.w) : make_float2(v10.x, v10.y);
        e110 = s10 ? make_float2(v10.x, v10.y) : make_float2(v10.z, v10.w);
        e011 = s11 ? make_float2(v11.z, v11.w) : make_float2(v11.x, v11.y);
        e111 = s11 ? make_float2(v11.x, v11.y) : make_float2(v11.z, v11.w);
    } else {
        unsigned hx1 = hx0 + 8u;
        e000 = __ldg((const float2*)(base + ((hx0 ^ a00) & MASK8)));
        e001 = __ldg((const float2*)(base + ((hx0 ^ a01) & MASK8)));
        e010 = __ldg((const float2*)(base + ((hx0 ^ a10) & MASK8)));
        e011 = __ldg((const float2*)(base + ((hx0 ^ a11) & MASK8)));
        e100 = __ldg((const float2*)(base + ((hx1 ^ a00) & MASK8)));
        e101 = __ldg((const float2*)(base + ((hx1 ^ a01) & MASK8)));
        e110 = __ldg((const float2*)(base + ((hx1 ^ a10) & MASK8)));
        e111 = __ldg((const float2*)(base + ((hx1 ^ a11) & MASK8)));
    }

    float2 c00 = lerp2(e000, e100, fx);
    float2 c01 = lerp2(e001, e101, fx);
    float2 c10 = lerp2(e010, e110, fx);
    float2 c11 = lerp2(e011, e111, fx);
    float2 c0  = lerp2(c00, c10, fy);
    float2 c1  = lerp2(c01, c11, fy);
    return lerp2(c0, c1, fz);
}

// interleave low 10 bits of v with two zero bits (Morton helper)
__device__ __forceinline__ unsigned part1by2(unsigned v) {
    v = (v | (v << 16)) & 0x030000FFu;
    v = (v | (v << 8))  & 0x0300F00Fu;
    v = (v | (v << 4))  & 0x030C30C3u;
    v = (v | (v << 2))  & 0x09249249u;
    return v;
}

__device__ __forceinline__ unsigned bucket_key(float px, float py, float pz) {
    unsigned bx = min((unsigned)(px * (float)BX), (unsigned)(BX - 1));
    unsigned by = min((unsigned)(py * (float)BX), (unsigned)(BX - 1));
    unsigned bz = min((unsigned)(pz * (float)BX), (unsigned)(BX - 1));
    return part1by2(bx) | (part1by2(by) << 1) | (part1by2(bz) << 2);  // < 32768
}

// ---- single-pass bucketing: 8 points per thread, atomics batched first
// (8 independent atomic->store chains in flight per thread). Bound by the
// LSU atomic-accept floor (~4 cyc/op), not by latency.
__global__ void scatter8_kernel(const float* __restrict__ x, unsigned nocts) {
    unsigned q = blockIdx.x * blockDim.x + threadIdx.x;
    if (q >= nocts) return;
    const float4* xv = (const float4*)(x + 24u * q);
    float4 v0 = __ldg(xv + 0), v1 = __ldg(xv + 1), v2 = __ldg(xv + 2);
    float4 v3 = __ldg(xv + 3), v4 = __ldg(xv + 4), v5 = __ldg(xv + 5);
    float vals[24] = {v0.x, v0.y, v0.z, v0.w, v1.x, v1.y, v1.z, v1.w,
                      v2.x, v2.y, v2.z, v2.w, v3.x, v3.y, v3.z, v3.w,
                      v4.x, v4.y, v4.z, v4.w, v5.x, v5.y, v5.z, v5.w};
    unsigned key[8], pos[8];
    #pragma unroll
    for (int i = 0; i < 8; i++)
        key[i] = bucket_key(vals[3 * i], vals[3 * i + 1], vals[3 * i + 2]);
    #pragma unroll
    for (int i = 0; i < 8; i++)
        pos[i] = atomicAdd(&g_cnt[key[i]], 1u);
    unsigned i0 = 8u * q;
    #pragma unroll
    for (int i = 0; i < 8; i++) {
        if (pos[i] < CAP)
            g_xs[key[i] * CAP + pos[i]] =
                make_float4(vals[3 * i], vals[3 * i + 1], vals[3 * i + 2],
                            __uint_as_float(i0 + (unsigned)i));
    }
}

// ---- encode over bucket slots ----
// Grid covers all NBKT*CAP slots; each warp's 32 slots lie inside ONE
// bucket (CAP=128 -> 4 warps/bucket) so every gather instruction has all
// active lanes at the same level on one spatial bucket's points ->
// maximal cross-lane 128B-line merging (the binding resource).
// Output path: 8x8 in-register butterfly transpose within lane-groups of 8
// so each STG.128 instruction has 8 lanes co-writing one row's full 128B
// -> 4 distinct lines per STG (stores: 1 wf/pt).
// Empty warps (about half: slots past a bucket's fill) RETIRE immediately
// -- the early return (not a barrier-reaching branch) is load-bearing:
// it frees scheduler slots and L1 queue capacity for busy warps (R15's
// barrier variant cost +33us).
__global__ void __launch_bounds__(256, 3) encode_bucket_kernel(
    const float* __restrict__ emb,
    float* __restrict__ out,
    Res16 rr)
{
    unsigned idx = blockIdx.x * 256u + threadIdx.x;   // global slot
    unsigned bucket = idx >> 7;                       // CAP = 128
    unsigned slot   = idx & 127u;
    unsigned lane   = threadIdx.x & 31u;

    unsigned cnt = min(__ldg(g_cnt + bucket), CAP);
    bool valid = slot < cnt;
    unsigned vmask = __ballot_sync(0xFFFFFFFFu, valid);
    if (vmask == 0u) return;                          // whole warp empty

    float4 p = make_float4(0.f, 0.f, 0.f, 0.f);
    if (valid) p = g_xs[idx];
    unsigned pidx = __float_as_uint(p.w);

    const char* base = (const char*)emb;
    float4 c[8];                                      // chunk j = levels 2j,2j+1
    #pragma unroll
    for (int j = 0; j < 8; j++) c[j] = make_float4(0.f, 0.f, 0.f, 0.f);
    if (valid) {
        #pragma unroll
        for (int j = 0; j < 8; j++) {
            float2 f0 = enc_level(base + (size_t)(2 * j) * (size_t)(TBL * 8u),
                                  p.x, p.y, p.z, (float)rr.r[2 * j]);
            float2 f1 = enc_level(base + (size_t)(2 * j + 1) * (size_t)(TBL * 8u),
                                  p.x, p.y, p.z, (float)rr.r[2 * j + 1]);
            c[j] = make_float4(f0.x, f0.y, f1.x, f1.y);
        }
    }

    // 8x8 transpose within groups of 8 lanes: element (lane p, slot t)
    // -> (lane t, slot p) via 3 xor-swap stages (moves iff ((p^t)&m)!=0).
    #pragma unroll
    for (int m = 1; m < 8; m <<= 1) {
        bool upper = (lane & (unsigned)m) != 0u;
        #pragma unroll
        for (int s0 = 0; s0 < 8; s0++) {
            if (s0 & m) continue;
            int s1 = s0 | m;
            float4 send = upper ? c[s0] : c[s1];
            float4 recv;
            recv.x = __shfl_xor_sync(0xFFFFFFFFu, send.x, m);
            recv.y = __shfl_xor_sync(0xFFFFFFFFu, send.y, m);
            recv.z = __shfl_xor_sync(0xFFFFFFFFu, send.z, m);
            recv.w = __shfl_xor_sync(0xFFFFFFFFu, send.w, m);
            if (upper) c[s0] = recv; else c[s1] = recv;
        }
    }
    // now lane (g,j): c[k] = chunk j (cols 4j..4j+3) of point 8g+k

    unsigned j = lane & 7u;
    unsigned gb = lane & 24u;
    #pragma unroll
    for (unsigned k = 0; k < 8; k++) {
        unsigned src = gb + k;
        unsigned rowpt = __shfl_sync(0xFFFFFFFFu, pidx, src);
        if ((vmask >> src) & 1u)
            *(float4*)(out + (size_t)rowpt * 32u + 4u * j) = c[k];
    }
}

// ---- fallback (unsorted) for unexpected sizes ----
__global__ void __launch_bounds__(256, 4) hashenc_fallback_kernel(
    const float* __restrict__ x,
    const float* __restrict__ emb,
    float* __restrict__ out,
    unsigned npts, Res16 rr)
{
    unsigned tid = blockIdx.x * 256u + threadIdx.x;
    unsigned pt = tid >> 3;
    if (pt >= npts) return;
    unsigned chunk = tid & 7u;
    unsigned lvl = chunk * 2u;

    float px = __ldg(x + 3u * pt + 0u);
    float py = __ldg(x + 3u * pt + 1u);
    float pz = __ldg(x + 3u * pt + 2u);

    const char* base0 = (const char*)emb + (size_t)lvl * (size_t)(TBL * 8u);
    float r0 = (float)rr.r[lvl];
    float r1 = (float)rr.r[lvl + 1u];

    float2 f0 = enc_level(base0, px, py, pz, r0);
    float2 f1 = enc_level(base0 + (size_t)(TBL * 8u), px, py, pz, r1);

    float4 o = make_float4(f0.x, f0.y, f1.x, f1.y);
    *(float4*)(out + (size_t)pt * 32u + chunk * 4u) = o;
}

extern "C" void kernel_launch(void* const* d_in, const int* in_sizes, int n_in,
                              void* d_out, int out_size)
{
    const float* x   = (const float*)d_in[0];   // [2097152, 3] f32
    const float* emb = (const float*)d_in[1];   // [16, 524288, 2] f32
    float* out = (float*)d_out;                 // [2097152, 32] f32

    unsigned npts = (unsigned)(in_sizes[0] / 3);

    // Resolutions via the exact reference formula in double precision
    // (floor margins as small as 0.004 -> do NOT hardcode).
    Res16 rr;
    double b = exp((log(2048.0) - log(16.0)) / 15.0);
    for (int i = 0; i < 16; i++)
        rr.r[i] = (int)floor(16.0 * pow(b, (double)i));

    if (npts == NPTS) {
        void* cnt_ptr = nullptr;
        cudaGetSymbolAddress(&cnt_ptr, g_cnt);
        cudaMemsetAsync(cnt_ptr, 0, NBKT * sizeof(unsigned), 0);  // capturable memset node
        unsigned nocts = npts / 8u;
        scatter8_kernel<<<(nocts + 255u) / 256u, 256>>>(x, nocts);
        encode_bucket_kernel<<<(NBKT * CAP) / 256u, 256>>>(emb, out, rr);
    } else {
        unsigned total = npts * 8u;
        hashenc_fallback_kernel<<<(total + 255u) / 256u, 256>>>(x, emb, out, npts, rr);
    }
}

// round 17
// speedup vs baseline: 1.0767x; 1.0024x over previous
#include <cuda_runtime.h>
#include <math.h>

#define TBL    524288u                 // T = 2^19 entries per level
#define MASK8  ((TBL - 1u) * 8u)       // byte-space mask
#define MASK16 (MASK8 & ~8u)           // 16B-aligned byte mask
#define PR1    2654435761u
#define PR2    805459861u

#define NPTS   2097152u
#define BX     32                      // spatial buckets per axis
#define NBKT   (BX * BX * BX)          // 32768 buckets (~64 pts each)
#define CAP    128u                    // slots per bucket (mean 64 + 8 sigma)

struct Res16 { int r[16]; };

// ---- device scratch (static only; no cudaMalloc allowed) ----
__device__ unsigned g_cnt[NBKT];
__device__ float4   g_xs[NBKT * CAP];    // bucketed {x,y,z, bits(orig idx)} (64MB)

__device__ __forceinline__ float2 lerp2(float2 a, float2 b, float t) {
    return make_float2(fmaf(t, b.x - a.x, a.x), fmaf(t, b.y - a.y, a.y));
}

// One level of hash-grid trilinear interpolation; byte-space hashing.
// EVEN ix: both x-corners sit in one aligned 16B block -> single LDG.128.
// (Exact R10/R14 code shape -- ptxas schedules this form with full load
// batching; R12/R13/R15 perturbations all regressed. Do not "improve".)
__device__ __forceinline__ float2 enc_level(
    const char* __restrict__ base, float px, float py, float pz, float r)
{
    float xs = px * r, ys = py * r, zs = pz * r;
    int ix = (int)xs, iy = (int)ys, iz = (int)zs;
    float fx = xs - (float)ix;
    float fy = ys - (float)iy;
    float fz = zs - (float)iz;

    unsigned hx0 = ((unsigned)ix) << 3;
    unsigned hy0 = (unsigned)iy * (PR1 * 8u);
    unsigned hy1 = hy0 + (PR1 * 8u);
    unsigned hz0 = (unsigned)iz * (PR2 * 8u);
    unsigned hz1 = hz0 + (PR2 * 8u);
    unsigned a00 = hy0 ^ hz0;
    unsigned a01 = hy0 ^ hz1;
    unsigned a10 = hy1 ^ hz0;
    unsigned a11 = hy1 ^ hz1;

    float2 e000, e001, e010, e011, e100, e101, e110, e111;

    if ((hx0 & 8u) == 0u) {
        float4 v00 = __ldg((const float4*)(base + ((hx0 ^ a00) & MASK16)));
        float4 v01 = __ldg((const float4*)(base + ((hx0 ^ a01) & MASK16)));
        float4 v10 = __ldg((const float4*)(base + ((hx0 ^ a10) & MASK16)));
        float4 v11 = __ldg((const float4*)(base + ((hx0 ^ a11) & MASK16)));
        bool s00 = (a00 & 8u) != 0u;
        bool s01 = (a01 & 8u) != 0u;
        bool s10 = (a10 & 8u) != 0u;
        bool s11 = (a11 & 8u) != 0u;
        e000 = s00 ? make_float2(v00.z, v00.w) : make_float2(v00.x, v00.y);
        e100 = s00 ? make_float2(v00.x, v00.y) : make_float2(v00.z, v00.w);
        e001 = s01 ? make_float2(v01.z, v01.w) : make_float2(v01.x, v01.y);
        e101 = s01 ? make_float2(v01.x, v01.y) : make_float2(v01.z, v01.w);
        e010 = s10 ? make_float2(v10.z, v10.w) : make_float2(v10.x, v10.y);
        e110 = s10 ? make_float2(v10.x, v10.y) : make_float2(v10.z, v10.w);
        e011 = s11 ? make_float2(v11.z, v11.w) : make_float2(v11.x, v11.y);
        e111 = s11 ? make_float2(v11.x, v11.y) : make_float2(v11.z, v11.w);
    } else {
        unsigned hx1 = hx0 + 8u;
        e000 = __ldg((const float2*)(base + ((hx0 ^ a00) & MASK8)));
        e001 = __ldg((const float2*)(base + ((hx0 ^ a01) & MASK8)));
        e010 = __ldg((const float2*)(base + ((hx0 ^ a10) & MASK8)));
        e011 = __ldg((const float2*)(base + ((hx0 ^ a11) & MASK8)));
        e100 = __ldg((const float2*)(base + ((hx1 ^ a00) & MASK8)));
        e101 = __ldg((const float2*)(base + ((hx1 ^ a01) & MASK8)));
        e110 = __ldg((const float2*)(base + ((hx1 ^ a10) & MASK8)));
        e111 = __ldg((const float2*)(base + ((hx1 ^ a11) & MASK8)));
    }

    float2 c00 = lerp2(e000, e100, fx);
    float2 c01 = lerp2(e001, e101, fx);
    float2 c10 = lerp2(e010, e110, fx);
    float2 c11 = lerp2(e011, e111, fx);
    float2 c0  = lerp2(c00, c10, fy);
    float2 c1  = lerp2(c01, c11, fy);
    return lerp2(c0, c1, fz);
}

// interleave low 10 bits of v with two zero bits (Morton helper)
__device__ __forceinline__ unsigned part1by2(unsigned v) {
    v = (v | (v << 16)) & 0x030000FFu;
    v = (v | (v << 8))  & 0x0300F00Fu;
    v = (v | (v << 4))  & 0x030C30C3u;
    v = (v | (v << 2))  & 0x09249249u;
    return v;
}

__device__ __forceinline__ unsigned bucket_key(float px, float py, float pz) {
    unsigned bx = min((unsigned)(px * (float)BX), (unsigned)(BX - 1));
    unsigned by = min((unsigned)(py * (float)BX), (unsigned)(BX - 1));
    unsigned bz = min((unsigned)(pz * (float)BX), (unsigned)(BX - 1));
    return part1by2(bx) | (part1by2(by) << 1) | (part1by2(bz) << 2);  // < 32768
}

// ---- single-pass bucketing: 8 points per thread, atomics batched first
// (8 independent atomic->store chains in flight per thread). Bound by the
// LSU atomic-accept floor (~4 cyc/op), not by latency.
__global__ void scatter8_kernel(const float* __restrict__ x, unsigned nocts) {
    unsigned q = blockIdx.x * blockDim.x + threadIdx.x;
    if (q >= nocts) return;
    const float4* xv = (const float4*)(x + 24u * q);
    float4 v0 = __ldg(xv + 0), v1 = __ldg(xv + 1), v2 = __ldg(xv + 2);
    float4 v3 = __ldg(xv + 3), v4 = __ldg(xv + 4), v5 = __ldg(xv + 5);
    float vals[24] = {v0.x, v0.y, v0.z, v0.w, v1.x, v1.y, v1.z, v1.w,
                      v2.x, v2.y, v2.z, v2.w, v3.x, v3.y, v3.z, v3.w,
                      v4.x, v4.y, v4.z, v4.w, v5.x, v5.y, v5.z, v5.w};
    unsigned key[8], pos[8];
    #pragma unroll
    for (int i = 0; i < 8; i++)
        key[i] = bucket_key(vals[3 * i], vals[3 * i + 1], vals[3 * i + 2]);
    #pragma unroll
    for (int i = 0; i < 8; i++)
        pos[i] = atomicAdd(&g_cnt[key[i]], 1u);
    unsigned i0 = 8u * q;
    #pragma unroll
    for (int i = 0; i < 8; i++) {
        if (pos[i] < CAP)
            g_xs[key[i] * CAP + pos[i]] =
                make_float4(vals[3 * i], vals[3 * i + 1], vals[3 * i + 2],
                            __uint_as_float(i0 + (unsigned)i));
    }
}

// ---- encode over bucket slots ----
// Grid covers all NBKT*CAP slots; each warp's 32 slots lie inside ONE
// bucket (CAP=128 -> 4 warps/bucket) so every gather instruction has all
// active lanes at the same level on one spatial bucket's points ->
// maximal cross-lane 128B-line merging (the binding resource).
// Output path: 8x8 in-register butterfly transpose within lane-groups of 8
// so each STG.128 instruction has 8 lanes co-writing one row's full 128B
// -> 4 distinct lines per STG (stores: 1 wf/pt).
// Empty warps (about half: slots past a bucket's fill) RETIRE immediately
// -- the early return (not a barrier-reaching branch) is load-bearing:
// it frees scheduler slots and L1 queue capacity for busy warps (R15's
// barrier variant cost +33us).
__global__ void __launch_bounds__(256, 3) encode_bucket_kernel(
    const float* __restrict__ emb,
    float* __restrict__ out,
    Res16 rr)
{
    unsigned idx = blockIdx.x * 256u + threadIdx.x;   // global slot
    unsigned bucket = idx >> 7;                       // CAP = 128
    unsigned slot   = idx & 127u;
    unsigned lane   = threadIdx.x & 31u;

    unsigned cnt = min(__ldg(g_cnt + bucket), CAP);
    bool valid = slot < cnt;
    unsigned vmask = __ballot_sync(0xFFFFFFFFu, valid);
    if (vmask == 0u) return;                          // whole warp empty

    float4 p = make_float4(0.f, 0.f, 0.f, 0.f);
    if (valid) p = g_xs[idx];
    unsigned pidx = __float_as_uint(p.w);

    const char* base = (const char*)emb;
    float4 c[8];                                      // chunk j = levels 2j,2j+1
    #pragma unroll
    for (int j = 0; j < 8; j++) c[j] = make_float4(0.f, 0.f, 0.f, 0.f);
    if (valid) {
        #pragma unroll
        for (int j = 0; j < 8; j++) {
            float2 f0 = enc_level(base + (size_t)(2 * j) * (size_t)(TBL * 8u),
                                  p.x, p.y, p.z, (float)rr.r[2 * j]);
            float2 f1 = enc_level(base + (size_t)(2 * j + 1) * (size_t)(TBL * 8u),
                                  p.x, p.y, p.z, (float)rr.r[2 * j + 1]);
            c[j] = make_float4(f0.x, f0.y, f1.x, f1.y);
        }
    }

    // 8x8 transpose within groups of 8 lanes: element (lane p, slot t)
    // -> (lane t, slot p) via 3 xor-swap stages (moves iff ((p^t)&m)!=0).
    #pragma unroll
    for (int m = 1; m < 8; m <<= 1) {
        bool upper = (lane & (unsigned)m) != 0u;
        #pragma unroll
        for (int s0 = 0; s0 < 8; s0++) {
            if (s0 & m) continue;
            int s1 = s0 | m;
            float4 send = upper ? c[s0] : c[s1];
            float4 recv;
            recv.x = __shfl_xor_sync(0xFFFFFFFFu, send.x, m);
            recv.y = __shfl_xor_sync(0xFFFFFFFFu, send.y, m);
            recv.z = __shfl_xor_sync(0xFFFFFFFFu, send.z, m);
            recv.w = __shfl_xor_sync(0xFFFFFFFFu, send.w, m);
            if (upper) c[s0] = recv; else c[s1] = recv;
        }
    }
    // now lane (g,j): c[k] = chunk j (cols 4j..4j+3) of point 8g+k

    unsigned j = lane & 7u;
    unsigned gb = lane & 24u;
    #pragma unroll
    for (unsigned k = 0; k < 8; k++) {
        unsigned src = gb + k;
        unsigned rowpt = __shfl_sync(0xFFFFFFFFu, pidx, src);
        if ((vmask >> src) & 1u)
            *(float4*)(out + (size_t)rowpt * 32u + 4u * j) = c[k];
    }
}

// ---- fallback (unsorted) for unexpected sizes ----
__global__ void __launch_bounds__(256, 4) hashenc_fallback_kernel(
    const float* __restrict__ x,
    const float* __restrict__ emb,
    float* __restrict__ out,
    unsigned npts, Res16 rr)
{
    unsigned tid = blockIdx.x * 256u + threadIdx.x;
    unsigned pt = tid >> 3;
    if (pt >= npts) return;
    unsigned chunk = tid & 7u;
    unsigned lvl = chunk * 2u;

    float px = __ldg(x + 3u * pt + 0u);
    float py = __ldg(x + 3u * pt + 1u);
    float pz = __ldg(x + 3u * pt + 2u);

    const char* base0 = (const char*)emb + (size_t)lvl * (size_t)(TBL * 8u);
    float r0 = (float)rr.r[lvl];
    float r1 = (float)rr.r[lvl + 1u];

    float2 f0 = enc_level(base0, px, py, pz, r0);
    float2 f1 = enc_level(base0 + (size_t)(TBL * 8u), px, py, pz, r1);

    float4 o = make_float4(f0.x, f0.y, f1.x, f1.y);
    *(float4*)(out + (size_t)pt * 32u + chunk * 4u) = o;
}

extern "C" void kernel_launch(void* const* d_in, const int* in_sizes, int n_in,
                              void* d_out, int out_size)
{
    const float* x   = (const float*)d_in[0];   // [2097152, 3] f32
    const float* emb = (const float*)d_in[1];   // [16, 524288, 2] f32
    float* out = (float*)d_out;                 // [2097152, 32] f32

    unsigned npts = (unsigned)(in_sizes[0] / 3);

    // Resolutions via the exact reference formula in double precision
    // (floor margins as small as 0.004 -> do NOT hardcode).
    Res16 rr;
    double b = exp((log(2048.0) - log(16.0)) / 15.0);
    for (int i = 0; i < 16; i++)
        rr.r[i] = (int)floor(16.0 * pow(b, (double)i));

    if (npts == NPTS) {
        void* cnt_ptr = nullptr;
        cudaGetSymbolAddress(&cnt_ptr, g_cnt);
        cudaMemsetAsync(cnt_ptr, 0, NBKT * sizeof(unsigned), 0);  // capturable memset node
        unsigned nocts = npts / 8u;
        scatter8_kernel<<<(nocts + 255u) / 256u, 256>>>(x, nocts);
        encode_bucket_kernel<<<(NBKT * CAP) / 256u, 256>>>(emb, out, rr);
    } else {
        unsigned total = npts * 8u;
        hashenc_fallback_kernel<<<(total + 255u) / 256u, 256>>>(x, emb, out, npts, rr);
    }
}